// round 8
// baseline (speedup 1.0000x reference)
#include <cuda_runtime.h>
#include <cuda_fp16.h>
#include <mma.h>
#include <cstdint>

using namespace nvcuda;

// ---------------------------------------------------------------------------
// LinearRNN via two-stage chunked factorization (L=16, K=64 truncation).
//   Z  = Uc[16384x1024] @ Wf[1024x256]        (+ fused Xs epilogue)
//   Xs[c] = sum_b Z[c-4+b, 64b:64b+64] (+ A^{16c} x0 for c<4)
//   Y  = [Uc | Xs][16384x1088] @ Wy[1088x1024] (block-lower-triangular)
// 4 launches: [u-convert (zero-smem, full occ)] -> [setup (64 blocks, 64KB)]
//   -> [gemm1 + fused Xs] -> [stage2].
// R7 lesson: heterogeneous fusion taxes the light branch — the 64KB smem
// reservation throttled the DRAM-bound conversion to 887 GB/s. Split them.
// ---------------------------------------------------------------------------

#define STAGE_H 17920               // halves per pipeline stage (A 9216 + B 8704)
#define SMEM_3S (3 * STAGE_H * 2)   // 107520 bytes

// ------------------------- static device scratch ---------------------------
__device__ float  g_xfix[4 * 64];           // A^{16c} x0
__device__ __half g_Wf[1024 * 256];         // stage-1 weights
__device__ __half g_Wy[1088 * 1024];        // stage-2 weights
__device__ float  g_Z [16384 * 256];        // stage-1 partials
__device__ __half g_Xs[16384 * 64];         // chunk-start states
__device__ __half g_u16[262144 * 64];       // u in fp16
__device__ int    g_flag[128];              // gemm1 tile-pair completion

// ------------------------------ helpers ------------------------------------
__device__ __forceinline__ uint32_t smem_addr(const void* p) {
    return (uint32_t)__cvta_generic_to_shared(p);
}
#define CP16(dst, src) \
    asm volatile("cp.async.cg.shared.global [%0], [%1], 16;" :: "r"(dst), "l"(src))
#define CP_COMMIT() asm volatile("cp.async.commit_group;" ::: "memory")
#define CP_WAIT1()  asm volatile("cp.async.wait_group 1;" ::: "memory")
#define CP_WAIT0()  asm volatile("cp.async.wait_group 0;" ::: "memory")

__device__ __forceinline__ void mm_acc(const float* Sa, const float* Sb, int tid,
                                       float acc[4][4]) {
    int r0 = (tid >> 4) << 2, c0 = (tid & 15) << 2;
    for (int k = 0; k < 64; k++) {
        float4 b = *(const float4*)&Sb[k * 64 + c0];
#pragma unroll
        for (int i = 0; i < 4; i++) {
            float a = Sa[(r0 + i) * 64 + k];
            acc[i][0] += a * b.x; acc[i][1] += a * b.y;
            acc[i][2] += a * b.z; acc[i][3] += a * b.w;
        }
    }
}

// ---------------- kernel 1: u fp32 -> fp16 (zero smem, full occ) ------------
__global__ __launch_bounds__(256)
void prepass_u16(const float* __restrict__ u) {
    size_t idx = ((size_t)blockIdx.x * 256 + threadIdx.x) * 16;
#pragma unroll
    for (int h = 0; h < 2; h++) {
        float4 a = *(const float4*)(u + idx + h * 8);
        float4 b = *(const float4*)(u + idx + h * 8 + 4);
        __half2 h0 = __floats2half2_rn(a.x, a.y), h1 = __floats2half2_rn(a.z, a.w);
        __half2 h2 = __floats2half2_rn(b.x, b.y), h3 = __floats2half2_rn(b.z, b.w);
        uint4 pk;
        pk.x = *(uint32_t*)&h0; pk.y = *(uint32_t*)&h1;
        pk.z = *(uint32_t*)&h2; pk.w = *(uint32_t*)&h3;
        *(uint4*)(g_u16 + idx + h * 8) = pk;
    }
}

// --------------- kernel 2: weight setup (64 independent blocks) -------------
// Block q: P_q = prod_bits A^(2^i) via local squaring chain (powers commute),
// then Wf slot, Hp_{q+1} scatter, G_q, D diag, triangular zeros, xfix.
__global__ __launch_bounds__(256)
void setup_powers(const float* __restrict__ A,  const float* __restrict__ Bm,
                  const float* __restrict__ Cm, const float* __restrict__ Dm,
                  const float* __restrict__ x0) {
    extern __shared__ float S[];                 // 4 x 4096 floats (64 KB)
    const int tid = threadIdx.x;
    const int q = blockIdx.x;
    const int r0 = (tid >> 4) << 2, c0 = (tid & 15) << 2;
    float* Sr = S;           float* Sp = S + 4096;     // P_q ping-pong
    float* cur = S + 8192;   float* spare = S + 12288; // A^(2^i) chain

    if (q == 0 && tid < 128) g_flag[tid] = 0;          // reset gemm1 flags

    for (int k = tid; k < 4096; k += 256) {
        cur[k] = A[k];
        Sr[k]  = ((k >> 6) == (k & 63)) ? 1.0f : 0.0f;
    }
    __syncthreads();

    for (int i = 0; i < 6; i++) {                      // P_q = prod A^(2^i)
        bool mul = (q >> i) & 1;
        bool sq  = (i < 5);
        float am[4][4] = {}, as[4][4] = {};
        if (mul) mm_acc(Sr, cur, tid, am);
        if (sq)  mm_acc(cur, cur, tid, as);
        if (mul) {
#pragma unroll
            for (int a2 = 0; a2 < 4; a2++)
#pragma unroll
                for (int b2 = 0; b2 < 4; b2++)
                    Sp[(r0 + a2) * 64 + c0 + b2] = am[a2][b2];
        }
        if (sq) {
#pragma unroll
            for (int a2 = 0; a2 < 4; a2++)
#pragma unroll
                for (int b2 = 0; b2 < 4; b2++)
                    spare[(r0 + a2) * 64 + c0 + b2] = as[a2][b2];
        }
        __syncthreads();
        if (mul) { float* t = Sr; Sr = Sp; Sp = t; }
        if (sq)  { float* t = cur; cur = spare; spare = t; }
    }

    float* Sf = cur;                                   // chain buffers dead
    // Mx_q = P_q @ B -> Sp
    for (int k = tid; k < 4096; k += 256) Sf[k] = Bm[k];
    __syncthreads();
    {
        float acc[4][4] = {};
        mm_acc(Sr, Sf, tid, acc);
        __syncthreads();
#pragma unroll
        for (int a2 = 0; a2 < 4; a2++)
#pragma unroll
            for (int b2 = 0; b2 < 4; b2++)
                Sp[(r0 + a2) * 64 + c0 + b2] = acc[a2][b2];
    }
    __syncthreads();
    // Wf slot: q = 63-16b-r  ->  b=(63-q)>>4, r=(63-q)&15
    {
        int bb = (63 - q) >> 4, rr = (63 - q) & 15;
        for (int idx = tid; idx < 4096; idx += 256) {
            int j = idx >> 6, n = idx & 63;
            g_Wf[(size_t)(64 * rr + j) * 256 + 64 * bb + n] =
                __float2half_rn(Sp[n * 64 + j]);
        }
    }
    for (int k = tid; k < 4096; k += 256) Sf[k] = Cm[k];
    __syncthreads();
    if (q < 15) {  // Hp_{q+1} = C @ Mx_q -> blocks (s, s+q+1)
        float acc[4][4] = {};
        mm_acc(Sf, Sp, tid, acc);
        int m = q + 1;
        for (int s = 0; s + m < 16; s++) {
            int dt = s + m;
#pragma unroll
            for (int i2 = 0; i2 < 4; i2++)
#pragma unroll
                for (int j = 0; j < 4; j++)
                    g_Wy[(size_t)(64 * s + c0 + j) * 1024 + 64 * dt + r0 + i2] =
                        __float2half_rn(acc[i2][j]);
        }
    }
    if (q < 16) {  // G_q = C @ P_q (Xs rows) + D on diagonal
        float acc[4][4] = {};
        mm_acc(Sf, Sr, tid, acc);
#pragma unroll
        for (int i2 = 0; i2 < 4; i2++)
#pragma unroll
            for (int j = 0; j < 4; j++)
                g_Wy[(size_t)(1024 + c0 + j) * 1024 + 64 * q + r0 + i2] =
                    __float2half_rn(acc[i2][j]);
        for (int idx = tid; idx < 4096; idx += 256) {
            int p = idx >> 6, j = idx & 63;
            g_Wy[(size_t)(64 * q + j) * 1024 + 64 * q + p] = __float2half_rn(Dm[idx]);
        }
    }
    // zeros for dt < s
    for (int z = q; z < 120; z += 64) {
        int s = 1;
        while ((s * (s + 1)) / 2 <= z) s++;
        int dt = z - (s * (s - 1)) / 2;
        for (int idx = tid; idx < 4096; idx += 256) {
            int j = idx >> 6, p = idx & 63;
            g_Wy[(size_t)(64 * s + j) * 1024 + 64 * dt + p] = __half(0.0f);
        }
    }
    if ((q & 15) == 0 && tid < 64) {                   // xfix[c] = A^{16c} x0
        int c = q >> 4;
        float accx = 0.0f;
        for (int k = 0; k < 64; k++) accx += Sr[tid * 64 + k] * x0[k];
        g_xfix[c * 64 + tid] = accx;
    }
}

// ----------- kernel 3: Z = Uc @ Wf, fused Xs epilogue via flags -------------
__global__ __launch_bounds__(256, 2)
void gemm1() {
    extern __shared__ __half smh[];
    const int tid = threadIdx.x;
    const int mt = blockIdx.x >> 1, nt = blockIdx.x & 1;
    const int c0 = mt * 128, ncol0 = nt * 128;

    auto load = [&](int s, int kt) {
        __half* Ab = smh + s * STAGE_H;
        __half* Bb = smh + s * STAGE_H + 9216;
        for (int idx = tid; idx < 1024; idx += 256) {
            int i = idx >> 3, cc = (idx & 7) << 3;
            CP16(smem_addr(Ab + i * 72 + cc),
                 g_u16 + (size_t)(c0 + i) * 1024 + kt * 64 + cc);
        }
        for (int idx = tid; idx < 1024; idx += 256) {
            int r = idx >> 4, cc = (idx & 15) << 3;
            CP16(smem_addr(Bb + r * 136 + cc),
                 g_Wf + (size_t)(kt * 64 + r) * 256 + ncol0 + cc);
        }
        CP_COMMIT();
    };

    const int w = tid >> 5;
    const int wr = w >> 2, wc = w & 3;
    wmma::fragment<wmma::accumulator, 16, 16, 16, float> acc[4][2];
#pragma unroll
    for (int tr = 0; tr < 4; tr++)
#pragma unroll
        for (int n = 0; n < 2; n++) wmma::fill_fragment(acc[tr][n], 0.0f);

    load(0, 0);
    load(1, 1);
    int sidx = 0;
    for (int it = 0; it < 16; it++) {
        if (it + 1 < 16) CP_WAIT1(); else CP_WAIT0();
        __syncthreads();
        if (it + 2 < 16) load((sidx + 2) % 3, it + 2);
        const __half* Ab = smh + sidx * STAGE_H;
        const __half* Bb = smh + sidx * STAGE_H + 9216;
#pragma unroll
        for (int kk = 0; kk < 4; kk++) {
            wmma::fragment<wmma::matrix_b, 16, 16, 16, __half, wmma::row_major> fb[2];
#pragma unroll
            for (int n = 0; n < 2; n++)
                wmma::load_matrix_sync(fb[n], Bb + (kk * 16) * 136 + wc * 32 + n * 16, 136);
#pragma unroll
            for (int tr = 0; tr < 4; tr++) {
                wmma::fragment<wmma::matrix_a, 16, 16, 16, __half, wmma::row_major> fa;
                wmma::load_matrix_sync(fa, Ab + (wr * 64 + tr * 16) * 72 + kk * 16, 72);
#pragma unroll
                for (int n = 0; n < 2; n++)
                    wmma::mma_sync(acc[tr][n], fa, fb[n], acc[tr][n]);
            }
        }
        if (++sidx == 3) sidx = 0;
    }

#pragma unroll
    for (int tr = 0; tr < 4; tr++)
#pragma unroll
        for (int n = 0; n < 2; n++)
            wmma::store_matrix_sync(
                g_Z + (size_t)(c0 + wr * 64 + tr * 16) * 256 + ncol0 + wc * 32 + n * 16,
                acc[tr][n], 256, wmma::mem_row_major);

    // ---- fused Xs epilogue (flag handshake; grid=256 fits in one wave) ----
    __threadfence();
    __syncthreads();
    if (tid == 0) atomicAdd(&g_flag[mt], 1);
    if (nt == 1) {
        if (tid == 0) {
            while (*(volatile int*)&g_flag[mt] < 2) {}
            if (mt > 0) while (*(volatile int*)&g_flag[mt - 1] < 2) {}
        }
        __syncthreads();
        __threadfence();
        for (int idx = tid; idx < 8192; idx += 256) {
            int c = c0 + (idx >> 6), n = idx & 63;
            float v = (c < 4) ? g_xfix[c * 64 + n] : 0.0f;
#pragma unroll
            for (int b = 0; b < 4; b++) {
                int cp = c - 4 + b;
                if (cp >= 0) v += g_Z[(size_t)cp * 256 + 64 * b + n];
            }
            g_Xs[(size_t)c * 64 + n] = __float2half_rn(v);
        }
    }
}

// ------------------------------ stage 2 ------------------------------------
__global__ __launch_bounds__(256, 2)
void stage2(float* __restrict__ y) {
    extern __shared__ __half smh[];
    const int tid = threadIdx.x;
    const int mt = blockIdx.x >> 3, nt = blockIdx.x & 7;
    const int c0 = mt * 128, ncol0 = nt * 128;
    const int kmax = (2 * nt + 2 < 16) ? 2 * nt + 2 : 16;
    const int niter = kmax + 1;

    auto load = [&](int s, int i2) {
        int kt = (i2 == niter - 1) ? 16 : i2;
        __half* Ab = smh + s * STAGE_H;
        __half* Bb = smh + s * STAGE_H + 9216;
        for (int idx = tid; idx < 1024; idx += 256) {
            int i = idx >> 3, cc = (idx & 7) << 3;
            const __half* src = (kt < 16)
                ? g_u16 + (size_t)(c0 + i) * 1024 + kt * 64 + cc
                : g_Xs + (size_t)(c0 + i) * 64 + cc;
            CP16(smem_addr(Ab + i * 72 + cc), src);
        }
        for (int idx = tid; idx < 1024; idx += 256) {
            int r = idx >> 4, cc = (idx & 15) << 3;
            CP16(smem_addr(Bb + r * 136 + cc),
                 g_Wy + (size_t)(kt * 64 + r) * 1024 + ncol0 + cc);
        }
        CP_COMMIT();
    };

    const int w = tid >> 5;
    const int wr = w >> 2, wc = w & 3;
    wmma::fragment<wmma::accumulator, 16, 16, 16, float> acc[4][2];
#pragma unroll
    for (int tr = 0; tr < 4; tr++)
#pragma unroll
        for (int n = 0; n < 2; n++) wmma::fill_fragment(acc[tr][n], 0.0f);

    load(0, 0);
    if (niter > 1) load(1, 1);
    int sidx = 0;
    for (int it = 0; it < niter; it++) {
        if (it + 1 < niter) CP_WAIT1(); else CP_WAIT0();
        __syncthreads();
        if (it + 2 < niter) load((sidx + 2) % 3, it + 2);
        const __half* Ab = smh + sidx * STAGE_H;
        const __half* Bb = smh + sidx * STAGE_H + 9216;
#pragma unroll
        for (int kk = 0; kk < 4; kk++) {
            wmma::fragment<wmma::matrix_b, 16, 16, 16, __half, wmma::row_major> fb[2];
#pragma unroll
            for (int n = 0; n < 2; n++)
                wmma::load_matrix_sync(fb[n], Bb + (kk * 16) * 136 + wc * 32 + n * 16, 136);
#pragma unroll
            for (int tr = 0; tr < 4; tr++) {
                wmma::fragment<wmma::matrix_a, 16, 16, 16, __half, wmma::row_major> fa;
                wmma::load_matrix_sync(fa, Ab + (wr * 64 + tr * 16) * 72 + kk * 16, 72);
#pragma unroll
                for (int n = 0; n < 2; n++)
                    wmma::mma_sync(acc[tr][n], fa, fb[n], acc[tr][n]);
            }
        }
        if (++sidx == 3) sidx = 0;
    }

#pragma unroll
    for (int tr = 0; tr < 4; tr++)
#pragma unroll
        for (int n = 0; n < 2; n++)
            wmma::store_matrix_sync(
                y + (size_t)(c0 + wr * 64 + tr * 16) * 1024 + ncol0 + wc * 32 + n * 16,
                acc[tr][n], 1024, wmma::mem_row_major);
}

// ---------------------------------------------------------------------------
extern "C" void kernel_launch(void* const* d_in, const int* in_sizes, int n_in,
                              void* d_out, int out_size) {
    const float* u  = (const float*)d_in[0];
    const float* x0 = (const float*)d_in[1];
    const float* A  = (const float*)d_in[2];
    const float* B  = (const float*)d_in[3];
    const float* C  = (const float*)d_in[4];
    const float* D  = (const float*)d_in[5];
    float* y = (float*)d_out;

    const int T  = in_sizes[0] / 64;     // 262144
    const int NC = T / 16;               // 16384

    static bool attr_set = false;
    if (!attr_set) {
        cudaFuncSetAttribute(setup_powers, cudaFuncAttributeMaxDynamicSharedMemorySize, 65536);
        cudaFuncSetAttribute(gemm1,  cudaFuncAttributeMaxDynamicSharedMemorySize, SMEM_3S);
        cudaFuncSetAttribute(stage2, cudaFuncAttributeMaxDynamicSharedMemorySize, SMEM_3S);
        attr_set = true;
    }

    prepass_u16<<<T * 64 / 4096, 256>>>(u);
    setup_powers<<<64, 256, 65536>>>(A, B, C, D, x0);
    gemm1<<<(NC / 128) * 2, 256, SMEM_3S>>>();
    stage2<<<(NC / 128) * 8, 256, SMEM_3S>>>(y);
}

// round 9
// speedup vs baseline: 1.0365x; 1.0365x over previous
#include <cuda_runtime.h>
#include <cuda_fp16.h>
#include <mma.h>
#include <cstdint>

using namespace nvcuda;

// ---------------------------------------------------------------------------
// LinearRNN via two-stage chunked factorization (L=16, K=64 truncation).
//   Z  = Uc[16384x1024] @ Wf[1024x256]        (+ Xs epilogue, flag-gated)
//   Xs[c] = sum_b Z[c-4+b, 64b:64b+64] (+ A^{16c} x0 for c<4)
//   Y  = [Uc | Xs][16384x1088] @ Wy[1088x1024] (block-lower-triangular)
// 3 launches: [u-convert] -> [setup, 64 blocks] -> [FUSED gemm1+stage2].
// In the fused kernel, stage2 blocks only wait for Xs at the single k-iter
// that consumes it (kt==16) -> gemm1 overlaps ~90% of stage2's work.
// Producers are bids 0..255 (< first wave of 296) -> deadlock-free.
// ---------------------------------------------------------------------------

#define STAGE_H 17920               // halves per pipeline stage (A 9216 + B 8704)
#define SMEM_3S (3 * STAGE_H * 2)   // 107520 bytes

// ------------------------- static device scratch ---------------------------
__device__ float  g_xfix[4 * 64];           // A^{16c} x0
__device__ __half g_Wf[1024 * 256];         // stage-1 weights
__device__ __half g_Wy[1088 * 1024];        // stage-2 weights
__device__ float  g_Z [16384 * 256];        // stage-1 partials
__device__ __half g_Xs[16384 * 64];         // chunk-start states
__device__ __half g_u16[262144 * 64];       // u in fp16
__device__ int    g_flag[128];              // Z tile-pair completion
__device__ int    g_xsflag[128];            // Xs[mt] ready

// ------------------------------ helpers ------------------------------------
__device__ __forceinline__ uint32_t smem_addr(const void* p) {
    return (uint32_t)__cvta_generic_to_shared(p);
}
#define CP16(dst, src) \
    asm volatile("cp.async.cg.shared.global [%0], [%1], 16;" :: "r"(dst), "l"(src))
#define CP_COMMIT() asm volatile("cp.async.commit_group;" ::: "memory")
#define CP_WAIT1()  asm volatile("cp.async.wait_group 1;" ::: "memory")
#define CP_WAIT0()  asm volatile("cp.async.wait_group 0;" ::: "memory")

__device__ __forceinline__ void mm_acc(const float* Sa, const float* Sb, int tid,
                                       float acc[4][4]) {
    int r0 = (tid >> 4) << 2, c0 = (tid & 15) << 2;
    for (int k = 0; k < 64; k++) {
        float4 b = *(const float4*)&Sb[k * 64 + c0];
#pragma unroll
        for (int i = 0; i < 4; i++) {
            float a = Sa[(r0 + i) * 64 + k];
            acc[i][0] += a * b.x; acc[i][1] += a * b.y;
            acc[i][2] += a * b.z; acc[i][3] += a * b.w;
        }
    }
}

// ---------------- kernel 1: u fp32 -> fp16 (fully coalesced) ----------------
__global__ __launch_bounds__(256)
void prepass_u16(const float* __restrict__ u) {
    size_t i4 = ((size_t)blockIdx.x * 256 + threadIdx.x) * 4;
    float4 a = *(const float4*)(u + i4);
    __half2 h0 = __floats2half2_rn(a.x, a.y), h1 = __floats2half2_rn(a.z, a.w);
    uint2 pk;
    pk.x = *(uint32_t*)&h0; pk.y = *(uint32_t*)&h1;
    *(uint2*)(g_u16 + i4) = pk;
}

// --------------- kernel 2: weight setup (64 independent blocks) -------------
__global__ __launch_bounds__(256)
void setup_powers(const float* __restrict__ A,  const float* __restrict__ Bm,
                  const float* __restrict__ Cm, const float* __restrict__ Dm,
                  const float* __restrict__ x0) {
    extern __shared__ float S[];                 // 4 x 4096 floats (64 KB)
    const int tid = threadIdx.x;
    const int q = blockIdx.x;
    const int r0 = (tid >> 4) << 2, c0 = (tid & 15) << 2;
    float* Sr = S;           float* Sp = S + 4096;     // P_q ping-pong
    float* cur = S + 8192;   float* spare = S + 12288; // A^(2^i) chain

    if (q == 0 && tid < 128) { g_flag[tid] = 0; g_xsflag[tid] = 0; }

    for (int k = tid; k < 4096; k += 256) {
        cur[k] = A[k];
        Sr[k]  = ((k >> 6) == (k & 63)) ? 1.0f : 0.0f;
    }
    __syncthreads();

    for (int i = 0; i < 6; i++) {                      // P_q = prod A^(2^i)
        bool mul = (q >> i) & 1;
        bool sq  = (i < 5);
        float am[4][4] = {}, as[4][4] = {};
        if (mul) mm_acc(Sr, cur, tid, am);
        if (sq)  mm_acc(cur, cur, tid, as);
        if (mul) {
#pragma unroll
            for (int a2 = 0; a2 < 4; a2++)
#pragma unroll
                for (int b2 = 0; b2 < 4; b2++)
                    Sp[(r0 + a2) * 64 + c0 + b2] = am[a2][b2];
        }
        if (sq) {
#pragma unroll
            for (int a2 = 0; a2 < 4; a2++)
#pragma unroll
                for (int b2 = 0; b2 < 4; b2++)
                    spare[(r0 + a2) * 64 + c0 + b2] = as[a2][b2];
        }
        __syncthreads();
        if (mul) { float* t = Sr; Sr = Sp; Sp = t; }
        if (sq)  { float* t = cur; cur = spare; spare = t; }
    }

    float* Sf = cur;
    // Mx_q = P_q @ B -> Sp
    for (int k = tid; k < 4096; k += 256) Sf[k] = Bm[k];
    __syncthreads();
    {
        float acc[4][4] = {};
        mm_acc(Sr, Sf, tid, acc);
        __syncthreads();
#pragma unroll
        for (int a2 = 0; a2 < 4; a2++)
#pragma unroll
            for (int b2 = 0; b2 < 4; b2++)
                Sp[(r0 + a2) * 64 + c0 + b2] = acc[a2][b2];
    }
    __syncthreads();
    // Wf slot: q = 63-16b-r
    {
        int bb = (63 - q) >> 4, rr = (63 - q) & 15;
        for (int idx = tid; idx < 4096; idx += 256) {
            int j = idx >> 6, n = idx & 63;
            g_Wf[(size_t)(64 * rr + j) * 256 + 64 * bb + n] =
                __float2half_rn(Sp[n * 64 + j]);
        }
    }
    for (int k = tid; k < 4096; k += 256) Sf[k] = Cm[k];
    __syncthreads();
    if (q < 15) {  // Hp_{q+1} = C @ Mx_q -> blocks (s, s+q+1)
        float acc[4][4] = {};
        mm_acc(Sf, Sp, tid, acc);
        int m = q + 1;
        for (int s = 0; s + m < 16; s++) {
            int dt = s + m;
#pragma unroll
            for (int i2 = 0; i2 < 4; i2++)
#pragma unroll
                for (int j = 0; j < 4; j++)
                    g_Wy[(size_t)(64 * s + c0 + j) * 1024 + 64 * dt + r0 + i2] =
                        __float2half_rn(acc[i2][j]);
        }
    }
    if (q < 16) {  // G_q = C @ P_q (Xs rows) + D on diagonal
        float acc[4][4] = {};
        mm_acc(Sf, Sr, tid, acc);
#pragma unroll
        for (int i2 = 0; i2 < 4; i2++)
#pragma unroll
            for (int j = 0; j < 4; j++)
                g_Wy[(size_t)(1024 + c0 + j) * 1024 + 64 * q + r0 + i2] =
                    __float2half_rn(acc[i2][j]);
        for (int idx = tid; idx < 4096; idx += 256) {
            int p = idx >> 6, j = idx & 63;
            g_Wy[(size_t)(64 * q + j) * 1024 + 64 * q + p] = __float2half_rn(Dm[idx]);
        }
    }
    // zeros for dt < s
    for (int z = q; z < 120; z += 64) {
        int s = 1;
        while ((s * (s + 1)) / 2 <= z) s++;
        int dt = z - (s * (s - 1)) / 2;
        for (int idx = tid; idx < 4096; idx += 256) {
            int j = idx >> 6, p = idx & 63;
            g_Wy[(size_t)(64 * s + j) * 1024 + 64 * dt + p] = __half(0.0f);
        }
    }
    if ((q & 15) == 0 && tid < 64) {                   // xfix[c] = A^{16c} x0
        int c = q >> 4;
        float accx = 0.0f;
        for (int k = 0; k < 64; k++) accx += Sr[tid * 64 + k] * x0[k];
        g_xfix[c * 64 + tid] = accx;
    }
}

// ------------- kernel 3: FUSED gemm1 (bids 0..255) + stage2 -----------------
__global__ __launch_bounds__(256, 2)
void mainfuse(float* __restrict__ y) {
    extern __shared__ __half smh[];
    const int tid = threadIdx.x;
    const int w = tid >> 5;
    const int wr = w >> 2, wc = w & 3;                 // 2x4 warp grid

    if (blockIdx.x < 256) {
        // ======================= gemm1: Z = Uc @ Wf =======================
        const int mt = blockIdx.x >> 1, nt = blockIdx.x & 1;
        const int c0 = mt * 128, ncol0 = nt * 128;

        auto load = [&](int s, int kt) {
            __half* Ab = smh + s * STAGE_H;
            __half* Bb = smh + s * STAGE_H + 9216;
            for (int idx = tid; idx < 1024; idx += 256) {
                int i = idx >> 3, cc = (idx & 7) << 3;
                CP16(smem_addr(Ab + i * 72 + cc),
                     g_u16 + (size_t)(c0 + i) * 1024 + kt * 64 + cc);
            }
            for (int idx = tid; idx < 1024; idx += 256) {
                int r = idx >> 4, cc = (idx & 15) << 3;
                CP16(smem_addr(Bb + r * 136 + cc),
                     g_Wf + (size_t)(kt * 64 + r) * 256 + ncol0 + cc);
            }
            CP_COMMIT();
        };

        wmma::fragment<wmma::accumulator, 16, 16, 16, float> acc[4][2];
#pragma unroll
        for (int tr = 0; tr < 4; tr++)
#pragma unroll
            for (int n = 0; n < 2; n++) wmma::fill_fragment(acc[tr][n], 0.0f);

        load(0, 0);
        load(1, 1);
        int sidx = 0;
        for (int it = 0; it < 16; it++) {
            if (it + 1 < 16) CP_WAIT1(); else CP_WAIT0();
            __syncthreads();
            if (it + 2 < 16) load((sidx + 2) % 3, it + 2);
            const __half* Ab = smh + sidx * STAGE_H;
            const __half* Bb = smh + sidx * STAGE_H + 9216;
#pragma unroll
            for (int kk = 0; kk < 4; kk++) {
                wmma::fragment<wmma::matrix_b, 16, 16, 16, __half, wmma::row_major> fb[2];
#pragma unroll
                for (int n = 0; n < 2; n++)
                    wmma::load_matrix_sync(fb[n], Bb + (kk * 16) * 136 + wc * 32 + n * 16, 136);
#pragma unroll
                for (int tr = 0; tr < 4; tr++) {
                    wmma::fragment<wmma::matrix_a, 16, 16, 16, __half, wmma::row_major> fa;
                    wmma::load_matrix_sync(fa, Ab + (wr * 64 + tr * 16) * 72 + kk * 16, 72);
#pragma unroll
                    for (int n = 0; n < 2; n++)
                        wmma::mma_sync(acc[tr][n], fa, fb[n], acc[tr][n]);
                }
            }
            if (++sidx == 3) sidx = 0;
        }

#pragma unroll
        for (int tr = 0; tr < 4; tr++)
#pragma unroll
            for (int n = 0; n < 2; n++)
                wmma::store_matrix_sync(
                    g_Z + (size_t)(c0 + wr * 64 + tr * 16) * 256 + ncol0 + wc * 32 + n * 16,
                    acc[tr][n], 256, wmma::mem_row_major);

        // ---- Xs epilogue: pair handshake, then publish xs_flag[mt] ----
        __threadfence();
        __syncthreads();
        if (tid == 0) atomicAdd(&g_flag[mt], 1);
        if (nt == 1) {
            if (tid == 0) {
                while (*(volatile int*)&g_flag[mt] < 2) {}
                if (mt > 0) while (*(volatile int*)&g_flag[mt - 1] < 2) {}
            }
            __syncthreads();
            __threadfence();
            for (int idx = tid; idx < 8192; idx += 256) {
                int c = c0 + (idx >> 6), n = idx & 63;
                float v = (c < 4) ? g_xfix[c * 64 + n] : 0.0f;
#pragma unroll
                for (int b = 0; b < 4; b++) {
                    int cp = c - 4 + b;
                    if (cp >= 0) v += g_Z[(size_t)cp * 256 + 64 * b + n];
                }
                g_Xs[(size_t)c * 64 + n] = __float2half_rn(v);
            }
            __threadfence();
            __syncthreads();
            if (tid == 0) *(volatile int*)&g_xsflag[mt] = 1;
        }
        return;
    }

    // ====================== stage2: Y = [Uc|Xs] @ Wy ======================
    const int s2 = blockIdx.x - 256;
    const int mt = s2 >> 3, nt = s2 & 7;
    const int c0 = mt * 128, ncol0 = nt * 128;
    const int kmax = (2 * nt + 2 < 16) ? 2 * nt + 2 : 16;
    const int niter = kmax + 1;

    auto load = [&](int s, int i2) {
        int kt = (i2 == niter - 1) ? 16 : i2;
        if (kt == 16) {                       // Xs tile: wait for producer
            if (tid == 0) while (*(volatile int*)&g_xsflag[mt] == 0) {}
            __syncthreads();
            __threadfence();
        }
        __half* Ab = smh + s * STAGE_H;
        __half* Bb = smh + s * STAGE_H + 9216;
        for (int idx = tid; idx < 1024; idx += 256) {
            int i = idx >> 3, cc = (idx & 7) << 3;
            const __half* src = (kt < 16)
                ? g_u16 + (size_t)(c0 + i) * 1024 + kt * 64 + cc
                : g_Xs + (size_t)(c0 + i) * 64 + cc;
            CP16(smem_addr(Ab + i * 72 + cc), src);
        }
        for (int idx = tid; idx < 1024; idx += 256) {
            int r = idx >> 4, cc = (idx & 15) << 3;
            CP16(smem_addr(Bb + r * 136 + cc),
                 g_Wy + (size_t)(kt * 64 + r) * 1024 + ncol0 + cc);
        }
        CP_COMMIT();
    };

    wmma::fragment<wmma::accumulator, 16, 16, 16, float> acc[4][2];
#pragma unroll
    for (int tr = 0; tr < 4; tr++)
#pragma unroll
        for (int n = 0; n < 2; n++) wmma::fill_fragment(acc[tr][n], 0.0f);

    load(0, 0);
    if (niter > 1) load(1, 1);
    int sidx = 0;
    for (int it = 0; it < niter; it++) {
        if (it + 1 < niter) CP_WAIT1(); else CP_WAIT0();
        __syncthreads();
        if (it + 2 < niter) load((sidx + 2) % 3, it + 2);
        const __half* Ab = smh + sidx * STAGE_H;
        const __half* Bb = smh + sidx * STAGE_H + 9216;
#pragma unroll
        for (int kk = 0; kk < 4; kk++) {
            wmma::fragment<wmma::matrix_b, 16, 16, 16, __half, wmma::row_major> fb[2];
#pragma unroll
            for (int n = 0; n < 2; n++)
                wmma::load_matrix_sync(fb[n], Bb + (kk * 16) * 136 + wc * 32 + n * 16, 136);
#pragma unroll
            for (int tr = 0; tr < 4; tr++) {
                wmma::fragment<wmma::matrix_a, 16, 16, 16, __half, wmma::row_major> fa;
                wmma::load_matrix_sync(fa, Ab + (wr * 64 + tr * 16) * 72 + kk * 16, 72);
#pragma unroll
                for (int n = 0; n < 2; n++)
                    wmma::mma_sync(acc[tr][n], fa, fb[n], acc[tr][n]);
            }
        }
        if (++sidx == 3) sidx = 0;
    }

#pragma unroll
    for (int tr = 0; tr < 4; tr++)
#pragma unroll
        for (int n = 0; n < 2; n++)
            wmma::store_matrix_sync(
                y + (size_t)(c0 + wr * 64 + tr * 16) * 1024 + ncol0 + wc * 32 + n * 16,
                acc[tr][n], 1024, wmma::mem_row_major);
}

// ---------------------------------------------------------------------------
extern "C" void kernel_launch(void* const* d_in, const int* in_sizes, int n_in,
                              void* d_out, int out_size) {
    const float* u  = (const float*)d_in[0];
    const float* x0 = (const float*)d_in[1];
    const float* A  = (const float*)d_in[2];
    const float* B  = (const float*)d_in[3];
    const float* C  = (const float*)d_in[4];
    const float* D  = (const float*)d_in[5];
    float* y = (float*)d_out;

    const int T  = in_sizes[0] / 64;     // 262144
    const int NC = T / 16;               // 16384

    static bool attr_set = false;
    if (!attr_set) {
        cudaFuncSetAttribute(setup_powers, cudaFuncAttributeMaxDynamicSharedMemorySize, 65536);
        cudaFuncSetAttribute(mainfuse, cudaFuncAttributeMaxDynamicSharedMemorySize, SMEM_3S);
        attr_set = true;
    }

    prepass_u16<<<T * 64 / 1024, 256>>>(u);
    setup_powers<<<64, 256, 65536>>>(A, B, C, D, x0);
    mainfuse<<<256 + (NC / 128) * 8, 256, SMEM_3S>>>(y);
}

// round 10
// speedup vs baseline: 1.0513x; 1.0143x over previous
#include <cuda_runtime.h>
#include <cuda_fp16.h>
#include <mma.h>
#include <cstdint>

using namespace nvcuda;

// ---------------------------------------------------------------------------
// LinearRNN via two-stage chunked factorization (L=16, K=64 truncation).
//   Z  = Uc[16384x1024] @ Wf[1024x256]        (+ Xs epilogue, flag-gated)
//   Xs[c] = sum_b Z[c-4+b, 64b:64b+64] (+ A^{16c} x0 for c<4)
//   Y  = [Uc | Xs][16384x1088] @ Wy[1088x1024] (block-lower-triangular)
// Launch DAG (graph fork-join):  prepass ∥ setup  ->  gemm1  ->  stage2.
// R9 lesson: fusing stage2 with gemm1 converts overlap into dead residency
// (early-finishing stage2 CTAs spin resident while gemm1 runs). Split them;
// instead overlap the independent setup (latency-bound) with the prepass
// (bandwidth-bound) on a side stream.
// ---------------------------------------------------------------------------

#define STAGE_H 17920               // halves per pipeline stage (A 9216 + B 8704)
#define SMEM_3S (3 * STAGE_H * 2)   // 107520 bytes

// ------------------------- static device scratch ---------------------------
__device__ float  g_xfix[4 * 64];           // A^{16c} x0
__device__ __half g_Wf[1024 * 256];         // stage-1 weights
__device__ __half g_Wy[1088 * 1024];        // stage-2 weights
__device__ float  g_Z [16384 * 256];        // stage-1 partials
__device__ __half g_Xs[16384 * 64];         // chunk-start states
__device__ __half g_u16[262144 * 64];       // u in fp16
__device__ int    g_flag[128];              // Z tile-pair completion

// ------------------------------ helpers ------------------------------------
__device__ __forceinline__ uint32_t smem_addr(const void* p) {
    return (uint32_t)__cvta_generic_to_shared(p);
}
#define CP16(dst, src) \
    asm volatile("cp.async.cg.shared.global [%0], [%1], 16;" :: "r"(dst), "l"(src))
#define CP_COMMIT() asm volatile("cp.async.commit_group;" ::: "memory")
#define CP_WAIT1()  asm volatile("cp.async.wait_group 1;" ::: "memory")
#define CP_WAIT0()  asm volatile("cp.async.wait_group 0;" ::: "memory")

__device__ __forceinline__ void mm_acc(const float* Sa, const float* Sb, int tid,
                                       float acc[4][4]) {
    int r0 = (tid >> 4) << 2, c0 = (tid & 15) << 2;
    for (int k = 0; k < 64; k++) {
        float4 b = *(const float4*)&Sb[k * 64 + c0];
#pragma unroll
        for (int i = 0; i < 4; i++) {
            float a = Sa[(r0 + i) * 64 + k];
            acc[i][0] += a * b.x; acc[i][1] += a * b.y;
            acc[i][2] += a * b.z; acc[i][3] += a * b.w;
        }
    }
}

// ---------------- kernel 1: u fp32 -> fp16 (fully coalesced) ----------------
__global__ __launch_bounds__(256)
void prepass_u16(const float* __restrict__ u) {
    size_t i4 = ((size_t)blockIdx.x * 256 + threadIdx.x) * 4;
    float4 a = *(const float4*)(u + i4);
    __half2 h0 = __floats2half2_rn(a.x, a.y), h1 = __floats2half2_rn(a.z, a.w);
    uint2 pk;
    pk.x = *(uint32_t*)&h0; pk.y = *(uint32_t*)&h1;
    *(uint2*)(g_u16 + i4) = pk;
}

// --------------- kernel 2: weight setup (64 independent blocks) -------------
// Block q: P_q = prod_bits A^(2^i) via local squaring chain (powers commute),
// then Wf slot, Hp_{q+1} scatter, G_q, D diag, triangular zeros, xfix.
__global__ __launch_bounds__(256)
void setup_powers(const float* __restrict__ A,  const float* __restrict__ Bm,
                  const float* __restrict__ Cm, const float* __restrict__ Dm,
                  const float* __restrict__ x0) {
    extern __shared__ float S[];                 // 4 x 4096 floats (64 KB)
    const int tid = threadIdx.x;
    const int q = blockIdx.x;
    const int r0 = (tid >> 4) << 2, c0 = (tid & 15) << 2;
    float* Sr = S;           float* Sp = S + 4096;     // P_q ping-pong
    float* cur = S + 8192;   float* spare = S + 12288; // A^(2^i) chain

    if (q == 0 && tid < 128) g_flag[tid] = 0;

    for (int k = tid; k < 4096; k += 256) {
        cur[k] = A[k];
        Sr[k]  = ((k >> 6) == (k & 63)) ? 1.0f : 0.0f;
    }
    __syncthreads();

    for (int i = 0; i < 6; i++) {                      // P_q = prod A^(2^i)
        bool mul = (q >> i) & 1;
        bool sq  = (i < 5);
        float am[4][4] = {}, as[4][4] = {};
        if (mul) mm_acc(Sr, cur, tid, am);
        if (sq)  mm_acc(cur, cur, tid, as);
        if (mul) {
#pragma unroll
            for (int a2 = 0; a2 < 4; a2++)
#pragma unroll
                for (int b2 = 0; b2 < 4; b2++)
                    Sp[(r0 + a2) * 64 + c0 + b2] = am[a2][b2];
        }
        if (sq) {
#pragma unroll
            for (int a2 = 0; a2 < 4; a2++)
#pragma unroll
                for (int b2 = 0; b2 < 4; b2++)
                    spare[(r0 + a2) * 64 + c0 + b2] = as[a2][b2];
        }
        __syncthreads();
        if (mul) { float* t = Sr; Sr = Sp; Sp = t; }
        if (sq)  { float* t = cur; cur = spare; spare = t; }
    }

    float* Sf = cur;
    // Mx_q = P_q @ B -> Sp
    for (int k = tid; k < 4096; k += 256) Sf[k] = Bm[k];
    __syncthreads();
    {
        float acc[4][4] = {};
        mm_acc(Sr, Sf, tid, acc);
        __syncthreads();
#pragma unroll
        for (int a2 = 0; a2 < 4; a2++)
#pragma unroll
            for (int b2 = 0; b2 < 4; b2++)
                Sp[(r0 + a2) * 64 + c0 + b2] = acc[a2][b2];
    }
    __syncthreads();
    // Wf slot: q = 63-16b-r
    {
        int bb = (63 - q) >> 4, rr = (63 - q) & 15;
        for (int idx = tid; idx < 4096; idx += 256) {
            int j = idx >> 6, n = idx & 63;
            g_Wf[(size_t)(64 * rr + j) * 256 + 64 * bb + n] =
                __float2half_rn(Sp[n * 64 + j]);
        }
    }
    for (int k = tid; k < 4096; k += 256) Sf[k] = Cm[k];
    __syncthreads();
    if (q < 15) {  // Hp_{q+1} = C @ Mx_q -> blocks (s, s+q+1)
        float acc[4][4] = {};
        mm_acc(Sf, Sp, tid, acc);
        int m = q + 1;
        for (int s = 0; s + m < 16; s++) {
            int dt = s + m;
#pragma unroll
            for (int i2 = 0; i2 < 4; i2++)
#pragma unroll
                for (int j = 0; j < 4; j++)
                    g_Wy[(size_t)(64 * s + c0 + j) * 1024 + 64 * dt + r0 + i2] =
                        __float2half_rn(acc[i2][j]);
        }
    }
    if (q < 16) {  // G_q = C @ P_q (Xs rows) + D on diagonal
        float acc[4][4] = {};
        mm_acc(Sf, Sr, tid, acc);
#pragma unroll
        for (int i2 = 0; i2 < 4; i2++)
#pragma unroll
            for (int j = 0; j < 4; j++)
                g_Wy[(size_t)(1024 + c0 + j) * 1024 + 64 * q + r0 + i2] =
                    __float2half_rn(acc[i2][j]);
        for (int idx = tid; idx < 4096; idx += 256) {
            int p = idx >> 6, j = idx & 63;
            g_Wy[(size_t)(64 * q + j) * 1024 + 64 * q + p] = __float2half_rn(Dm[idx]);
        }
    }
    // zeros for dt < s
    for (int z = q; z < 120; z += 64) {
        int s = 1;
        while ((s * (s + 1)) / 2 <= z) s++;
        int dt = z - (s * (s - 1)) / 2;
        for (int idx = tid; idx < 4096; idx += 256) {
            int j = idx >> 6, p = idx & 63;
            g_Wy[(size_t)(64 * s + j) * 1024 + 64 * dt + p] = __half(0.0f);
        }
    }
    if ((q & 15) == 0 && tid < 64) {                   // xfix[c] = A^{16c} x0
        int c = q >> 4;
        float accx = 0.0f;
        for (int k = 0; k < 64; k++) accx += Sr[tid * 64 + k] * x0[k];
        g_xfix[c * 64 + tid] = accx;
    }
}

// ----------- kernel 3: Z = Uc @ Wf, fused Xs epilogue via flags -------------
__global__ __launch_bounds__(256, 2)
void gemm1() {
    extern __shared__ __half smh[];
    const int tid = threadIdx.x;
    const int mt = blockIdx.x >> 1, nt = blockIdx.x & 1;
    const int c0 = mt * 128, ncol0 = nt * 128;

    auto load = [&](int s, int kt) {
        __half* Ab = smh + s * STAGE_H;
        __half* Bb = smh + s * STAGE_H + 9216;
        for (int idx = tid; idx < 1024; idx += 256) {
            int i = idx >> 3, cc = (idx & 7) << 3;
            CP16(smem_addr(Ab + i * 72 + cc),
                 g_u16 + (size_t)(c0 + i) * 1024 + kt * 64 + cc);
        }
        for (int idx = tid; idx < 1024; idx += 256) {
            int r = idx >> 4, cc = (idx & 15) << 3;
            CP16(smem_addr(Bb + r * 136 + cc),
                 g_Wf + (size_t)(kt * 64 + r) * 256 + ncol0 + cc);
        }
        CP_COMMIT();
    };

    const int w = tid >> 5;
    const int wr = w >> 2, wc = w & 3;
    wmma::fragment<wmma::accumulator, 16, 16, 16, float> acc[4][2];
#pragma unroll
    for (int tr = 0; tr < 4; tr++)
#pragma unroll
        for (int n = 0; n < 2; n++) wmma::fill_fragment(acc[tr][n], 0.0f);

    load(0, 0);
    load(1, 1);
    int sidx = 0;
    for (int it = 0; it < 16; it++) {
        if (it + 1 < 16) CP_WAIT1(); else CP_WAIT0();
        __syncthreads();
        if (it + 2 < 16) load((sidx + 2) % 3, it + 2);
        const __half* Ab = smh + sidx * STAGE_H;
        const __half* Bb = smh + sidx * STAGE_H + 9216;
#pragma unroll
        for (int kk = 0; kk < 4; kk++) {
            wmma::fragment<wmma::matrix_b, 16, 16, 16, __half, wmma::row_major> fb[2];
#pragma unroll
            for (int n = 0; n < 2; n++)
                wmma::load_matrix_sync(fb[n], Bb + (kk * 16) * 136 + wc * 32 + n * 16, 136);
#pragma unroll
            for (int tr = 0; tr < 4; tr++) {
                wmma::fragment<wmma::matrix_a, 16, 16, 16, __half, wmma::row_major> fa;
                wmma::load_matrix_sync(fa, Ab + (wr * 64 + tr * 16) * 72 + kk * 16, 72);
#pragma unroll
                for (int n = 0; n < 2; n++)
                    wmma::mma_sync(acc[tr][n], fa, fb[n], acc[tr][n]);
            }
        }
        if (++sidx == 3) sidx = 0;
    }

#pragma unroll
    for (int tr = 0; tr < 4; tr++)
#pragma unroll
        for (int n = 0; n < 2; n++)
            wmma::store_matrix_sync(
                g_Z + (size_t)(c0 + wr * 64 + tr * 16) * 256 + ncol0 + wc * 32 + n * 16,
                acc[tr][n], 256, wmma::mem_row_major);

    // ---- fused Xs epilogue (flag handshake; grid=256 all resident) ----
    __threadfence();
    __syncthreads();
    if (tid == 0) atomicAdd(&g_flag[mt], 1);
    if (nt == 1) {
        if (tid == 0) {
            while (*(volatile int*)&g_flag[mt] < 2) {}
            if (mt > 0) while (*(volatile int*)&g_flag[mt - 1] < 2) {}
        }
        __syncthreads();
        __threadfence();
        for (int idx = tid; idx < 8192; idx += 256) {
            int c = c0 + (idx >> 6), n = idx & 63;
            float v = (c < 4) ? g_xfix[c * 64 + n] : 0.0f;
#pragma unroll
            for (int b = 0; b < 4; b++) {
                int cp = c - 4 + b;
                if (cp >= 0) v += g_Z[(size_t)cp * 256 + 64 * b + n];
            }
            g_Xs[(size_t)c * 64 + n] = __float2half_rn(v);
        }
    }
}

// ------------------------------ stage 2 ------------------------------------
__global__ __launch_bounds__(256, 2)
void stage2(float* __restrict__ y) {
    extern __shared__ __half smh[];
    const int tid = threadIdx.x;
    const int mt = blockIdx.x >> 3, nt = blockIdx.x & 7;
    const int c0 = mt * 128, ncol0 = nt * 128;
    const int kmax = (2 * nt + 2 < 16) ? 2 * nt + 2 : 16;
    const int niter = kmax + 1;

    auto load = [&](int s, int i2) {
        int kt = (i2 == niter - 1) ? 16 : i2;
        __half* Ab = smh + s * STAGE_H;
        __half* Bb = smh + s * STAGE_H + 9216;
        for (int idx = tid; idx < 1024; idx += 256) {
            int i = idx >> 3, cc = (idx & 7) << 3;
            const __half* src = (kt < 16)
                ? g_u16 + (size_t)(c0 + i) * 1024 + kt * 64 + cc
                : g_Xs + (size_t)(c0 + i) * 64 + cc;
            CP16(smem_addr(Ab + i * 72 + cc), src);
        }
        for (int idx = tid; idx < 1024; idx += 256) {
            int r = idx >> 4, cc = (idx & 15) << 3;
            CP16(smem_addr(Bb + r * 136 + cc),
                 g_Wy + (size_t)(kt * 64 + r) * 1024 + ncol0 + cc);
        }
        CP_COMMIT();
    };

    const int w = tid >> 5;
    const int wr = w >> 2, wc = w & 3;
    wmma::fragment<wmma::accumulator, 16, 16, 16, float> acc[4][2];
#pragma unroll
    for (int tr = 0; tr < 4; tr++)
#pragma unroll
        for (int n = 0; n < 2; n++) wmma::fill_fragment(acc[tr][n], 0.0f);

    load(0, 0);
    if (niter > 1) load(1, 1);
    int sidx = 0;
    for (int it = 0; it < niter; it++) {
        if (it + 1 < niter) CP_WAIT1(); else CP_WAIT0();
        __syncthreads();
        if (it + 2 < niter) load((sidx + 2) % 3, it + 2);
        const __half* Ab = smh + sidx * STAGE_H;
        const __half* Bb = smh + sidx * STAGE_H + 9216;
#pragma unroll
        for (int kk = 0; kk < 4; kk++) {
            wmma::fragment<wmma::matrix_b, 16, 16, 16, __half, wmma::row_major> fb[2];
#pragma unroll
            for (int n = 0; n < 2; n++)
                wmma::load_matrix_sync(fb[n], Bb + (kk * 16) * 136 + wc * 32 + n * 16, 136);
#pragma unroll
            for (int tr = 0; tr < 4; tr++) {
                wmma::fragment<wmma::matrix_a, 16, 16, 16, __half, wmma::row_major> fa;
                wmma::load_matrix_sync(fa, Ab + (wr * 64 + tr * 16) * 72 + kk * 16, 72);
#pragma unroll
                for (int n = 0; n < 2; n++)
                    wmma::mma_sync(acc[tr][n], fa, fb[n], acc[tr][n]);
            }
        }
        if (++sidx == 3) sidx = 0;
    }

#pragma unroll
    for (int tr = 0; tr < 4; tr++)
#pragma unroll
        for (int n = 0; n < 2; n++)
            wmma::store_matrix_sync(
                y + (size_t)(c0 + wr * 64 + tr * 16) * 1024 + ncol0 + wc * 32 + n * 16,
                acc[tr][n], 1024, wmma::mem_row_major);
}

// ---------------------------------------------------------------------------
extern "C" void kernel_launch(void* const* d_in, const int* in_sizes, int n_in,
                              void* d_out, int out_size) {
    const float* u  = (const float*)d_in[0];
    const float* x0 = (const float*)d_in[1];
    const float* A  = (const float*)d_in[2];
    const float* B  = (const float*)d_in[3];
    const float* C  = (const float*)d_in[4];
    const float* D  = (const float*)d_in[5];
    float* y = (float*)d_out;

    const int T  = in_sizes[0] / 64;     // 262144
    const int NC = T / 16;               // 16384

    static cudaStream_t s_side = nullptr;
    static cudaEvent_t ev_fork = nullptr, ev_join = nullptr;
    static bool attr_set = false;
    if (!attr_set) {
        cudaFuncSetAttribute(setup_powers, cudaFuncAttributeMaxDynamicSharedMemorySize, 65536);
        cudaFuncSetAttribute(gemm1,  cudaFuncAttributeMaxDynamicSharedMemorySize, SMEM_3S);
        cudaFuncSetAttribute(stage2, cudaFuncAttributeMaxDynamicSharedMemorySize, SMEM_3S);
        cudaStreamCreateWithFlags(&s_side, cudaStreamNonBlocking);
        cudaEventCreateWithFlags(&ev_fork, cudaEventDisableTiming);
        cudaEventCreateWithFlags(&ev_join, cudaEventDisableTiming);
        attr_set = true;
    }

    // Fork: setup (latency-bound) on side stream, concurrent with prepass
    // (bandwidth-bound) on the capture stream. Join before gemm1.
    cudaEventRecord(ev_fork, 0);
    cudaStreamWaitEvent(s_side, ev_fork, 0);
    setup_powers<<<64, 256, 65536, s_side>>>(A, B, C, D, x0);
    cudaEventRecord(ev_join, s_side);

    prepass_u16<<<T * 64 / 1024, 256>>>(u);

    cudaStreamWaitEvent(0, ev_join, 0);
    gemm1<<<(NC / 128) * 2, 256, SMEM_3S>>>();
    stage2<<<(NC / 128) * 8, 256, SMEM_3S>>>(y);
}